// round 1
// baseline (speedup 1.0000x reference)
#include <cuda_runtime.h>

// GRU: x[1024,784,1], Wi[384,1], bi[384], Wh[384,128], bh[384], Wfc[10,128], bfc[10]
// out: logits[1024,10] fp32
//
// Persistent-per-CTA design: 128 CTAs x 128 threads; each CTA owns 8 batch rows
// and runs the full 784-step recurrence locally. Wh lives in SMEM (fp32,
// transposed to [k][g] float4 layout for conflict-free vector loads). Thread i
// owns hidden index i and its 3 gates (r,z,n) for all 8 rows; accumulators are
// packed row-pairs driven by fma.rn.f32x2 (2 FMAs/instr).

#define HIDDEN 128
#define SEQ    784
#define BATCH  1024
#define ROWS   8
#define NCTA   (BATCH / ROWS)   // 128
#define G3     (3 * HIDDEN)     // 384
#define NT     128

#define WHS_FLOATS   (G3 * HIDDEN)          // 49152 floats = 196608 B
#define HBUF_FLOATS  (HIDDEN * ROWS)        // 1024 floats per buffer
#define SMEM_BYTES   ((WHS_FLOATS + 2 * HBUF_FLOATS) * 4)  // 204800 B

// ---- packed f32x2 helpers (sm_103a) ----
__device__ __forceinline__ unsigned long long pk2(float a, float b) {
    unsigned long long r;
    asm("mov.b64 %0, {%1, %2};" : "=l"(r) : "f"(a), "f"(b));
    return r;
}
__device__ __forceinline__ void upk2(unsigned long long v, float& a, float& b) {
    asm("mov.b64 {%0, %1}, %2;" : "=f"(a), "=f"(b) : "l"(v));
}
__device__ __forceinline__ void fma2(unsigned long long& acc,
                                     unsigned long long a,
                                     unsigned long long b) {
    asm("fma.rn.f32x2 %0, %1, %2, %0;" : "+l"(acc) : "l"(a), "l"(b));
}

__device__ __forceinline__ float fast_sigmoid(float x) {
    // 1/(1+e^-x); saturates cleanly at both ends (e->inf gives 0, e->0 gives 1)
    float e = __expf(-x);
    return __fdividef(1.0f, 1.0f + e);
}
__device__ __forceinline__ float fast_tanh(float x) {
    // 2*sigmoid(2x)-1; NaN-free at extremes
    float e = __expf(-2.0f * x);
    return fmaf(2.0f, __fdividef(1.0f, 1.0f + e), -1.0f);
}

extern __shared__ float smem[];

__global__ __launch_bounds__(NT, 1)
void gru_persistent_kernel(const float* __restrict__ x,
                           const float* __restrict__ Wi,
                           const float* __restrict__ bi,
                           const float* __restrict__ Wh,
                           const float* __restrict__ bh,
                           const float* __restrict__ Wfc,
                           const float* __restrict__ bfc,
                           float* __restrict__ out) {
    float4* Whs4  = reinterpret_cast<float4*>(smem);       // [HIDDEN/4][G3] float4
    float*  hbuf0 = smem + WHS_FLOATS;                     // [k][r] layout
    float*  hbuf1 = hbuf0 + HBUF_FLOATS;

    const int tid  = threadIdx.x;
    const int row0 = blockIdx.x * ROWS;

    // ---- one-time: stage Wh into SMEM as Whs4[k4*G3 + g] = Wh[g][4k4..4k4+3]
    const float4* Wh4 = reinterpret_cast<const float4*>(Wh);
    for (int idx = tid; idx < (HIDDEN / 4) * G3; idx += NT) {
        int k4 = idx / G3;
        int g  = idx - k4 * G3;
        Whs4[idx] = Wh4[g * (HIDDEN / 4) + k4];
    }
    for (int idx = tid; idx < HBUF_FLOATS; idx += NT) hbuf0[idx] = 0.0f;
    __syncthreads();

    // thread i owns hidden index i: gates g=i (r), i+128 (z), i+256 (n)
    const int   i   = tid;
    const float wi0 = Wi[i];
    const float wi1 = Wi[i + HIDDEN];
    const float wi2 = Wi[i + 2 * HIDDEN];
    const float br  = bi[i] + bh[i];
    const float bz  = bi[i + HIDDEN] + bh[i + HIDDEN];
    const float bni = bi[i + 2 * HIDDEN];
    const float bnh = bh[i + 2 * HIDDEN];

    float hprev[ROWS];
#pragma unroll
    for (int r = 0; r < ROWS; ++r) hprev[r] = 0.0f;

    const float* xrow = x + (long)row0 * SEQ;

#pragma unroll 1
    for (int t = 0; t < SEQ; ++t) {
        const float* hb = (t & 1) ? hbuf1 : hbuf0;
        float*       hw = (t & 1) ? hbuf0 : hbuf1;
        const ulonglong2* hp = reinterpret_cast<const ulonglong2*>(hb);

        // packed accumulators: row pairs (0,1)(2,3)(4,5)(6,7) for each gate
        unsigned long long ar[4], az[4], an[4];
#pragma unroll
        for (int p = 0; p < 4; ++p) { ar[p] = 0ull; az[p] = 0ull; an[p] = 0ull; }

#pragma unroll 4
        for (int k4 = 0; k4 < HIDDEN / 4; ++k4) {
            const float4 w0 = Whs4[k4 * G3 + i];
            const float4 w1 = Whs4[k4 * G3 + i + HIDDEN];
            const float4 w2 = Whs4[k4 * G3 + i + 2 * HIDDEN];
            const float wr4[4] = {w0.x, w0.y, w0.z, w0.w};
            const float wz4[4] = {w1.x, w1.y, w1.z, w1.w};
            const float wn4[4] = {w2.x, w2.y, w2.z, w2.w};
#pragma unroll
            for (int j = 0; j < 4; ++j) {
                const int k = 4 * k4 + j;
                const ulonglong2 hA = hp[2 * k + 0];  // rows 0-3 at this k
                const ulonglong2 hB = hp[2 * k + 1];  // rows 4-7 at this k
                const unsigned long long wr = pk2(wr4[j], wr4[j]);
                const unsigned long long wz = pk2(wz4[j], wz4[j]);
                const unsigned long long wn = pk2(wn4[j], wn4[j]);
                fma2(ar[0], hA.x, wr); fma2(ar[1], hA.y, wr);
                fma2(ar[2], hB.x, wr); fma2(ar[3], hB.y, wr);
                fma2(az[0], hA.x, wz); fma2(az[1], hA.y, wz);
                fma2(az[2], hB.x, wz); fma2(az[3], hB.y, wz);
                fma2(an[0], hA.x, wn); fma2(an[1], hA.y, wn);
                fma2(an[2], hB.x, wn); fma2(an[3], hB.y, wn);
            }
        }

        // x values for this step (broadcast LDG, L1-resident)
        float xv[ROWS];
#pragma unroll
        for (int r = 0; r < ROWS; ++r) xv[r] = __ldg(xrow + (long)r * SEQ + t);

        // gates + state update
#pragma unroll
        for (int p = 0; p < 4; ++p) {
            float gr0, gr1, gz0, gz1, gn0, gn1;
            upk2(ar[p], gr0, gr1);
            upk2(az[p], gz0, gz1);
            upk2(an[p], gn0, gn1);
            const int r0 = 2 * p, r1 = 2 * p + 1;

            {
                const float rr = fast_sigmoid(gr0 + fmaf(xv[r0], wi0, br));
                const float zz = fast_sigmoid(gz0 + fmaf(xv[r0], wi1, bz));
                const float nn = fast_tanh(fmaf(xv[r0], wi2, bni) + rr * (gn0 + bnh));
                hprev[r0] = nn + zz * (hprev[r0] - nn);
            }
            {
                const float rr = fast_sigmoid(gr1 + fmaf(xv[r1], wi0, br));
                const float zz = fast_sigmoid(gz1 + fmaf(xv[r1], wi1, bz));
                const float nn = fast_tanh(fmaf(xv[r1], wi2, bni) + rr * (gn1 + bnh));
                hprev[r1] = nn + zz * (hprev[r1] - nn);
            }
        }

        // write h_new for next step: hw[k=i][r]
        float4* hw4 = reinterpret_cast<float4*>(hw + i * ROWS);
        hw4[0] = make_float4(hprev[0], hprev[1], hprev[2], hprev[3]);
        hw4[1] = make_float4(hprev[4], hprev[5], hprev[6], hprev[7]);
        __syncthreads();
    }

    // ---- final FC: logits = h @ Wfc^T + bfc
    // last write (t=783, odd) went to hbuf0
    if (tid < ROWS * 10) {
        const int r = tid / 10;
        const int o = tid - r * 10;
        float s = bfc[o];
        const float* wf = Wfc + o * HIDDEN;
#pragma unroll 8
        for (int k = 0; k < HIDDEN; ++k) s = fmaf(hbuf0[k * ROWS + r], wf[k], s);
        out[(long)(row0 + r) * 10 + o] = s;
    }
}

extern "C" void kernel_launch(void* const* d_in, const int* in_sizes, int n_in,
                              void* d_out, int out_size) {
    const float* x   = (const float*)d_in[0];
    const float* Wi  = (const float*)d_in[1];
    const float* bi  = (const float*)d_in[2];
    const float* Wh  = (const float*)d_in[3];
    const float* bh  = (const float*)d_in[4];
    const float* Wfc = (const float*)d_in[5];
    const float* bfc = (const float*)d_in[6];
    float* out = (float*)d_out;

    cudaFuncSetAttribute(gru_persistent_kernel,
                         cudaFuncAttributeMaxDynamicSharedMemorySize, SMEM_BYTES);
    gru_persistent_kernel<<<NCTA, NT, SMEM_BYTES>>>(x, Wi, bi, Wh, bh, Wfc, bfc, out);
}

// round 3
// speedup vs baseline: 2.3652x; 2.3652x over previous
#include <cuda_runtime.h>
#include <cstdint>

// GRU via warp-level HMMA (mma.sync m16n8k16 bf16->fp32), no 'a'-feature PTX.
// 128 CTAs x 256 threads; each CTA owns 8 batch rows for all 784 steps.
// Per step: gh[384,8] = Wh[384,128] @ h[8,128]^T as 24 M-tiles x 8 K-tiles.
// Precision: Wh = W_hi + W_lo (bf16 split), h = h_hi + h_lo (bf16 split);
// gh = W_hi*h_hi + W_hi*h_lo + W_lo*h_hi accumulated in fp32 C-frags.
// W_hi: register-resident A fragments (96 regs/thread).
// W_lo: SMEM, fragment-interleaved, one ld.shared.v4 per fragment.

#define HID   128
#define SEQ   784
#define ROWS  8
#define NT    256
#define NCTA  128

#define GH_STRIDE 40                   // bytes per gate row (8 n * 4B + 8 pad)
#define B_STRIDE  272                  // bytes per n row of h tiles (256 + 16 pad)

#define OFF_WLO 0                      // 24*8*32*16 = 98304 B
#define OFF_GH  98304                  // 384*40 = 15360 B
#define OFF_BH  (98304 + 15360)        // 8*272 = 2176 B
#define OFF_BL  (OFF_BH + 2176)        // 2176 B
#define SMEM_BYTES (OFF_BL + 2176)     // 120192 B

__device__ __forceinline__ uint16_t f2bf(float f) {
    uint16_t h;
    asm("cvt.rn.bf16.f32 %0, %1;" : "=h"(h) : "f"(f));
    return h;
}
__device__ __forceinline__ float bf2f(uint16_t h) {
    return __uint_as_float((uint32_t)h << 16);
}
__device__ __forceinline__ uint32_t pack_hi(float w0, float w1) {
    return (uint32_t)f2bf(w0) | ((uint32_t)f2bf(w1) << 16);
}
__device__ __forceinline__ uint32_t pack_lo(float w0, float w1) {
    float r0 = w0 - bf2f(f2bf(w0));
    float r1 = w1 - bf2f(f2bf(w1));
    return (uint32_t)f2bf(r0) | ((uint32_t)f2bf(r1) << 16);
}
__device__ __forceinline__ void mma16816(float* c, const uint32_t* a,
                                         uint32_t b0, uint32_t b1) {
    asm volatile(
        "mma.sync.aligned.m16n8k16.row.col.f32.bf16.bf16.f32 "
        "{%0,%1,%2,%3}, {%4,%5,%6,%7}, {%8,%9}, {%0,%1,%2,%3};"
        : "+f"(c[0]), "+f"(c[1]), "+f"(c[2]), "+f"(c[3])
        : "r"(a[0]), "r"(a[1]), "r"(a[2]), "r"(a[3]), "r"(b0), "r"(b1));
}
__device__ __forceinline__ float fast_sigmoid(float x) {
    float e = __expf(-x);
    return __fdividef(1.0f, 1.0f + e);
}
__device__ __forceinline__ float fast_tanh(float x) {
    float e = __expf(-2.0f * x);
    return fmaf(2.0f, __fdividef(1.0f, 1.0f + e), -1.0f);
}

extern __shared__ __align__(16) char smem[];

__global__ __launch_bounds__(NT, 1)
void gru_hmma_kernel(const float* __restrict__ x,
                     const float* __restrict__ Wi,
                     const float* __restrict__ bi,
                     const float* __restrict__ Wh,
                     const float* __restrict__ bh,
                     const float* __restrict__ Wfc,
                     const float* __restrict__ bfc,
                     float* __restrict__ out) {
    const int tid  = threadIdx.x;
    const int lane = tid & 31;
    const int wid  = tid >> 5;
    const int row0 = blockIdx.x * ROWS;

    // ---- prologue: W_hi -> register A-fragments; W_lo -> SMEM fragment array
    uint32_t af[3][8][4];
#pragma unroll
    for (int j = 0; j < 3; ++j) {
        const int m = wid * 3 + j;                 // M-tile 0..23 (gates 16m..16m+15)
#pragma unroll
        for (int kt = 0; kt < 8; ++kt) {
            uint32_t lo[4];
#pragma unroll
            for (int r = 0; r < 4; ++r) {
                const int g = m * 16 + (lane >> 2) + ((r & 1) ? 8 : 0);
                const int k = kt * 16 + (lane & 3) * 2 + ((r & 2) ? 8 : 0);
                const float w0 = Wh[g * HID + k];
                const float w1 = Wh[g * HID + k + 1];
                af[j][kt][r] = pack_hi(w0, w1);
                lo[r]        = pack_lo(w0, w1);
            }
            *(uint4*)(smem + OFF_WLO + (((m * 8) + kt) * 32 + lane) * 16) =
                make_uint4(lo[0], lo[1], lo[2], lo[3]);
        }
    }
    // zero h hi/lo tiles (contiguous 2*2176 B)
    for (int idx = tid; idx < (2 * 2176) / 4; idx += NT)
        ((uint32_t*)(smem + OFF_BH))[idx] = 0u;

    // gate-thread constants (tid < 128 meaningful; masked index keeps loads legal)
    const int   i   = tid & 127;
    const float wi0 = Wi[i];
    const float wi1 = Wi[i + HID];
    const float wi2 = Wi[i + 2 * HID];
    const float br  = bi[i] + bh[i];
    const float bz  = bi[i + HID] + bh[i + HID];
    const float bni = bi[i + 2 * HID];
    const float bnh = bh[i + 2 * HID];

    float hprev[ROWS];
#pragma unroll
    for (int r = 0; r < ROWS; ++r) hprev[r] = 0.0f;

    const float* xrow = x + (long)row0 * SEQ;
    const bool is_gate = (tid < 128);

    __syncthreads();

#pragma unroll 1
    for (int t = 0; t < SEQ; ++t) {
        // ---- phase 1: all 8 warps do the 3-pass MMA ----
        float C[3][4];
#pragma unroll
        for (int j = 0; j < 3; ++j)
#pragma unroll
            for (int r = 0; r < 4; ++r) C[j][r] = 0.0f;

        float xv[ROWS];
        if (is_gate) {
#pragma unroll
            for (int r = 0; r < ROWS; ++r) xv[r] = __ldg(xrow + (long)r * SEQ + t);
        }

        const int nb = (lane >> 2) * B_STRIDE;          // n row base
#pragma unroll
        for (int kt = 0; kt < 8; ++kt) {
            const int kb = kt * 32 + (lane & 3) * 4;    // byte offset of k within row
            const uint32_t bh0 = *(const uint32_t*)(smem + OFF_BH + nb + kb);
            const uint32_t bh1 = *(const uint32_t*)(smem + OFF_BH + nb + kb + 16);
            const uint32_t bl0 = *(const uint32_t*)(smem + OFF_BL + nb + kb);
            const uint32_t bl1 = *(const uint32_t*)(smem + OFF_BL + nb + kb + 16);
#pragma unroll
            for (int j = 0; j < 3; ++j) {
                mma16816(C[j], af[j][kt], bh0, bh1);          // W_hi * h_hi
                mma16816(C[j], af[j][kt], bl0, bl1);          // W_hi * h_lo
                const uint4 wl = *(const uint4*)(smem + OFF_WLO +
                                  (((wid * 3 + j) * 8 + kt) * 32 + lane) * 16);
                const uint32_t wla[4] = {wl.x, wl.y, wl.z, wl.w};
                mma16816(C[j], wla, bh0, bh1);                // W_lo * h_hi
            }
        }

        // ---- phase 2: spill gh C-frags to SMEM [g][n] (stride 40B) ----
#pragma unroll
        for (int j = 0; j < 3; ++j) {
            const int g0 = (wid * 3 + j) * 16 + (lane >> 2);
            const int cb = (lane & 3) * 8;
            *(float2*)(smem + OFF_GH + g0 * GH_STRIDE + cb) =
                make_float2(C[j][0], C[j][1]);
            *(float2*)(smem + OFF_GH + (g0 + 8) * GH_STRIDE + cb) =
                make_float2(C[j][2], C[j][3]);
        }
        __syncthreads();

        // ---- phase 3: gate math on 128 threads; write next h hi/lo tiles ----
        if (is_gate) {
            float gr[8], gz[8], gn[8];
            const char* pr = smem + OFF_GH + i * GH_STRIDE;
            const char* pz = smem + OFF_GH + (i + 128) * GH_STRIDE;
            const char* pn = smem + OFF_GH + (i + 256) * GH_STRIDE;
#pragma unroll
            for (int q = 0; q < 4; ++q) {
                float2 a = *(const float2*)(pr + q * 8);
                gr[2 * q] = a.x; gr[2 * q + 1] = a.y;
                float2 b = *(const float2*)(pz + q * 8);
                gz[2 * q] = b.x; gz[2 * q + 1] = b.y;
                float2 c = *(const float2*)(pn + q * 8);
                gn[2 * q] = c.x; gn[2 * q + 1] = c.y;
            }
#pragma unroll
            for (int r = 0; r < ROWS; ++r) {
                const float rr = fast_sigmoid(gr[r] + fmaf(xv[r], wi0, br));
                const float zz = fast_sigmoid(gz[r] + fmaf(xv[r], wi1, bz));
                const float nn = fast_tanh(fmaf(xv[r], wi2, bni) + rr * (gn[r] + bnh));
                const float h  = nn + zz * (hprev[r] - nn);
                hprev[r] = h;
                const uint16_t hb = f2bf(h);
                const uint16_t lb = f2bf(h - bf2f(hb));
                *(uint16_t*)(smem + OFF_BH + r * B_STRIDE + i * 2) = hb;
                *(uint16_t*)(smem + OFF_BL + r * B_STRIDE + i * 2) = lb;
            }
        }
        __syncthreads();
    }

    // ---- final FC: logits = h @ Wfc^T + bfc ----
    float* hf = (float*)(smem + OFF_GH);   // reuse: hf[k][n], 128x8 fp32
    if (is_gate) {
#pragma unroll
        for (int r = 0; r < ROWS; ++r) hf[i * ROWS + r] = hprev[r];
    }
    __syncthreads();

    if (tid < ROWS * 10) {
        const int r = tid / 10;
        const int o = tid - r * 10;
        float s = bfc[o];
        const float* wf = Wfc + o * HID;
#pragma unroll 8
        for (int k = 0; k < HID; ++k) s = fmaf(hf[k * ROWS + r], wf[k], s);
        out[(long)(row0 + r) * 10 + o] = s;
    }
}

extern "C" void kernel_launch(void* const* d_in, const int* in_sizes, int n_in,
                              void* d_out, int out_size) {
    const float* x   = (const float*)d_in[0];
    const float* Wi  = (const float*)d_in[1];
    const float* bi  = (const float*)d_in[2];
    const float* Wh  = (const float*)d_in[3];
    const float* bh  = (const float*)d_in[4];
    const float* Wfc = (const float*)d_in[5];
    const float* bfc = (const float*)d_in[6];
    float* out = (float*)d_out;

    cudaFuncSetAttribute(gru_hmma_kernel,
                         cudaFuncAttributeMaxDynamicSharedMemorySize, SMEM_BYTES);
    gru_hmma_kernel<<<NCTA, NT, SMEM_BYTES>>>(x, Wi, bi, Wh, bh, Wfc, bfc, out);
}